// round 10
// baseline (speedup 1.0000x reference)
#include <cuda_runtime.h>
#include <cuda_fp16.h>
#include <math.h>
#include <stdint.h>

// Problem constants (fixed shapes)
#define BATCH 2
#define TLEN  2048
#define EMB   1024
#define HEADS 16
#define HDIM  64
#define MROWS (BATCH * TLEN)   // 4096
#define SCALE 0.125f           // 1/sqrt(64)
#define LN_EPS 1e-5f

typedef unsigned long long ull;

// Scratch (device globals — no allocation allowed)
__device__ float g_K[MROWS * EMB];
__device__ float g_Q[MROWS * EMB];
__device__ float g_V[MROWS * EMB];
__device__ float g_A[MROWS * EMB];

__device__ __half g_xf[MROWS * EMB];
__device__ __half g_af[MROWS * EMB];
__device__ __half g_Wf[4 * EMB * EMB];

// ---------------------------------------------------------------------------
// Helpers
// ---------------------------------------------------------------------------
__device__ __forceinline__ uint32_t s2u(const void* p) {
    return (uint32_t)__cvta_generic_to_shared(p);
}

__device__ __forceinline__ void cp_async16(uint32_t saddr, const void* gaddr) {
    asm volatile("cp.async.cg.shared.global [%0], [%1], 16;"
                 :: "r"(saddr), "l"(gaddr) : "memory");
}

__device__ __forceinline__ void ldsm_x4(uint32_t r[4], uint32_t addr) {
    asm volatile("ldmatrix.sync.aligned.m8n8.x4.shared.b16 {%0,%1,%2,%3}, [%4];"
        : "=r"(r[0]), "=r"(r[1]), "=r"(r[2]), "=r"(r[3]) : "r"(addr));
}

__device__ __forceinline__ void mma_fp16(float c[4], const uint32_t a[4],
                                         uint32_t b0, uint32_t b1) {
    asm volatile(
        "mma.sync.aligned.m16n8k16.row.col.f32.f16.f16.f32 "
        "{%0,%1,%2,%3}, {%4,%5,%6,%7}, {%8,%9}, {%0,%1,%2,%3};"
        : "+f"(c[0]), "+f"(c[1]), "+f"(c[2]), "+f"(c[3])
        : "r"(a[0]), "r"(a[1]), "r"(a[2]), "r"(a[3]), "r"(b0), "r"(b1));
}

// Packed f32x2 ops (Blackwell; PTX-only, ptxas never auto-fuses)
__device__ __forceinline__ ull pk2(float lo, float hi) {
    ull r; asm("mov.b64 %0, {%1, %2};" : "=l"(r) : "f"(lo), "f"(hi)); return r;
}
__device__ __forceinline__ void up2(ull v, float& lo, float& hi) {
    asm("mov.b64 {%0, %1}, %2;" : "=f"(lo), "=f"(hi) : "l"(v));
}
__device__ __forceinline__ ull fma2(ull a, ull b, ull c) {
    ull d; asm("fma.rn.f32x2 %0, %1, %2, %3;" : "=l"(d) : "l"(a), "l"(b), "l"(c));
    return d;
}
__device__ __forceinline__ ull mul2(ull a, ull b) {
    ull d; asm("mul.rn.f32x2 %0, %1, %2;" : "=l"(d) : "l"(a), "l"(b));
    return d;
}

// ---------------------------------------------------------------------------
// Convert fp32 -> fp16. 4 elems/thread.
// ---------------------------------------------------------------------------
__global__ void __launch_bounds__(256) cvt_kernel(
    const float* __restrict__ X, __half* __restrict__ Y, int n4)
{
    int i = blockIdx.x * blockDim.x + threadIdx.x;
    if (i >= n4) return;
    float4 v = reinterpret_cast<const float4*>(X)[i];
    union { __half h[4]; uint2 u; } H;
    H.h[0] = __float2half(v.x);
    H.h[1] = __float2half(v.y);
    H.h[2] = __float2half(v.z);
    H.h[3] = __float2half(v.w);
    reinterpret_cast<uint2*>(Y)[i] = H.u;
}

// ---------------------------------------------------------------------------
// Tensor-core NT GEMM, single-pass fp16, fp32 accum: C = A @ B^T.
// Block tile 128x128x32, 256 threads, warp tile 32x64, double-buffered.
// ---------------------------------------------------------------------------
#define BM 128
#define BN 128
#define BK 32
#define LDSW 40
#define STG_ELEMS (128 * LDSW)
#define STAGE_ELEMS (2 * STG_ELEMS)
#define GEMM_SMEM (2 * STAGE_ELEMS * 2)   // 40960 B

__global__ void __launch_bounds__(256, 2) gemm_fp16_kernel(
    const __half* __restrict__ A, const __half* __restrict__ B,
    float* __restrict__ C, int M, int N, int K)
{
    extern __shared__ __half smem[];

    const int tid  = threadIdx.x;
    const int m0   = blockIdx.y * BM;
    const int n0   = blockIdx.x * BN;
    const int w    = tid >> 5;
    const int lane = tid & 31;
    const int wm   = (w >> 1) * 32;
    const int wn   = (w & 1) * 64;
    const int arow = lane & 15;
    const int acol = (lane >> 4) * 8;

    float acc[2][8][4];
    #pragma unroll
    for (int mf = 0; mf < 2; mf++)
        #pragma unroll
        for (int nf = 0; nf < 8; nf++)
            #pragma unroll
            for (int r = 0; r < 4; r++) acc[mf][nf][r] = 0.0f;

    const int NK = K / BK;

    auto load_stage = [&](int kc, int s) {
        const int k0 = kc * BK;
        __half* base = smem + s * STAGE_ELEMS;
        const uint32_t sb = s2u(base);
        #pragma unroll
        for (int j = 0; j < 2; j++) {
            int u   = tid + j * 256;
            int row = u >> 2;
            int c   = (u & 3) * 8;
            uint32_t so = (uint32_t)(row * LDSW + c) * 2;
            size_t ga = (size_t)(m0 + row) * K + k0 + c;
            size_t gb = (size_t)(n0 + row) * K + k0 + c;
            cp_async16(sb + 0 * STG_ELEMS * 2 + so, A + ga);
            cp_async16(sb + 1 * STG_ELEMS * 2 + so, B + gb);
        }
        asm volatile("cp.async.commit_group;");
    };

    load_stage(0, 0);

    for (int kc = 0; kc < NK; kc++) {
        if (kc + 1 < NK) {
            load_stage(kc + 1, (kc + 1) & 1);
            asm volatile("cp.async.wait_group 1;" ::: "memory");
        } else {
            asm volatile("cp.async.wait_group 0;" ::: "memory");
        }
        __syncthreads();

        const int s = kc & 1;
        __half (*sA)[LDSW] =
            reinterpret_cast<__half(*)[LDSW]>(smem + s * STAGE_ELEMS);
        __half (*sB)[LDSW] =
            reinterpret_cast<__half(*)[LDSW]>(smem + s * STAGE_ELEMS + STG_ELEMS);

        #pragma unroll
        for (int kf = 0; kf < 2; kf++) {
            uint32_t af[2][4];
            #pragma unroll
            for (int mf = 0; mf < 2; mf++)
                ldsm_x4(af[mf], s2u(&sA[wm + mf * 16 + arow][kf * 16 + acol]));
            #pragma unroll
            for (int nb = 0; nb < 4; nb++) {
                uint32_t bf[4];
                ldsm_x4(bf, s2u(&sB[wn + nb * 16 + arow][kf * 16 + acol]));
                #pragma unroll
                for (int mf = 0; mf < 2; mf++) {
                    mma_fp16(acc[mf][2 * nb],     af[mf], bf[0], bf[2]);
                    mma_fp16(acc[mf][2 * nb + 1], af[mf], bf[1], bf[3]);
                }
            }
        }
        __syncthreads();
    }

    #pragma unroll
    for (int mf = 0; mf < 2; mf++) {
        int row = m0 + wm + mf * 16 + (lane >> 2);
        #pragma unroll
        for (int nf = 0; nf < 8; nf++) {
            int col = n0 + wn + nf * 8 + (lane & 3) * 2;
            *reinterpret_cast<float2*>(&C[(size_t)row * N + col]) =
                make_float2(acc[mf][nf][0], acc[mf][nf][1]);
            *reinterpret_cast<float2*>(&C[(size_t)(row + 8) * N + col]) =
                make_float2(acc[mf][nf][2], acc[mf][nf][3]);
        }
    }
}

// ---------------------------------------------------------------------------
// Per-head LayerNorm over last dim (64). One warp per row. In-place.
// ---------------------------------------------------------------------------
__global__ void __launch_bounds__(256) ln_kernel(
    float* __restrict__ X, const float* __restrict__ w,
    const float* __restrict__ bias, int rows)
{
    int warp = (blockIdx.x * blockDim.x + threadIdx.x) >> 5;
    int lane = threadIdx.x & 31;
    if (warp >= rows) return;

    float* r = X + (size_t)warp * HDIM;
    float v0 = r[lane];
    float v1 = r[lane + 32];

    float sum = v0 + v1;
    #pragma unroll
    for (int o = 16; o > 0; o >>= 1) sum += __shfl_xor_sync(0xffffffffu, sum, o);
    float mu = sum * (1.0f / 64.0f);

    float d0 = v0 - mu, d1 = v1 - mu;
    float sq = d0 * d0 + d1 * d1;
    #pragma unroll
    for (int o = 16; o > 0; o >>= 1) sq += __shfl_xor_sync(0xffffffffu, sq, o);
    float inv = rsqrtf(sq * (1.0f / 64.0f) + LN_EPS);

    r[lane]      = d0 * inv * w[lane]      + bias[lane];
    r[lane + 32] = d1 * inv * w[lane + 32] + bias[lane + 32];
}

// ---------------------------------------------------------------------------
// Causal flash attention, packed f32x2 math (halves FFMA warp-inst count).
// One thread per query row, 64 queries per block.
// ---------------------------------------------------------------------------
#define SSTRIDE 68

__global__ void __launch_bounds__(64) attn_kernel(
    const float* __restrict__ Q, const float* __restrict__ K,
    const float* __restrict__ V, float* __restrict__ O)
{
    extern __shared__ float sm[];
    float* Ks  = sm;           // [64][64]
    float* Vs  = sm + 4096;    // [64][64]
    float* Ssc = sm + 8192;    // [64][SSTRIDE]

    const int tid = threadIdx.x;
    const int qb  = blockIdx.x;
    const int h   = blockIdx.y;
    const int b   = blockIdx.z;
    const int q   = qb * 64 + tid;

    // q row as 32 packed pairs, scale folded in
    const float* Qrow = Q + ((size_t)(b * TLEN + q) * HEADS + h) * HDIM;
    ull qr2[32];
    #pragma unroll
    for (int kk = 0; kk < 16; kk++) {
        float4 v = reinterpret_cast<const float4*>(Qrow)[kk];
        qr2[2 * kk + 0] = pk2(v.x * SCALE, v.y * SCALE);
        qr2[2 * kk + 1] = pk2(v.z * SCALE, v.w * SCALE);
    }

    ull acc2[32];
    #pragma unroll
    for (int kk = 0; kk < 32; kk++) acc2[kk] = 0ull;
    float mrun = -INFINITY;
    float lrun = 0.0f;

    float* myS = Ssc + tid * SSTRIDE;

    for (int j0 = 0; j0 <= qb * 64; j0 += 64) {
        __syncthreads();
        // float4 tile load: 16 iters, 4 rows per iter (16 threads/row)
        {
            const int lrow = tid >> 4;
            const int lcol = (tid & 15) * 4;
            #pragma unroll 4
            for (int i0 = 0; i0 < 64; i0 += 4) {
                int row = i0 + lrow;
                size_t gbase = ((size_t)(b * TLEN + j0 + row) * HEADS + h) * HDIM + lcol;
                *reinterpret_cast<float4*>(&Ks[row * 64 + lcol]) =
                    *reinterpret_cast<const float4*>(&K[gbase]);
                *reinterpret_cast<float4*>(&Vs[row * 64 + lcol]) =
                    *reinterpret_cast<const float4*>(&V[gbase]);
            }
        }
        __syncthreads();

        int jmax = q - j0 + 1;
        if (jmax > 64) jmax = 64;

        // pass 1: 4 keys/iter, 2 packed chains each -> 8 independent chains
        float tmax = -INFINITY;
        for (int j = 0; j < jmax; j += 4) {
            const ull* k0 = reinterpret_cast<const ull*>(&Ks[(j + 0) * 64]);
            const ull* k1 = reinterpret_cast<const ull*>(&Ks[(j + 1) * 64]);
            const ull* k2 = reinterpret_cast<const ull*>(&Ks[(j + 2) * 64]);
            const ull* k3 = reinterpret_cast<const ull*>(&Ks[(j + 3) * 64]);
            ull s0x = 0, s0y = 0, s1x = 0, s1y = 0;
            ull s2x = 0, s2y = 0, s3x = 0, s3y = 0;
            #pragma unroll
            for (int kk = 0; kk < 32; kk += 2) {
                s0x = fma2(qr2[kk],     k0[kk],     s0x);
                s0y = fma2(qr2[kk + 1], k0[kk + 1], s0y);
                s1x = fma2(qr2[kk],     k1[kk],     s1x);
                s1y = fma2(qr2[kk + 1], k1[kk + 1], s1y);
                s2x = fma2(qr2[kk],     k2[kk],     s2x);
                s2y = fma2(qr2[kk + 1], k2[kk + 1], s2y);
                s3x = fma2(qr2[kk],     k3[kk],     s3x);
                s3y = fma2(qr2[kk + 1], k3[kk + 1], s3y);
            }
            float a0, b0v, c0, d0, a1, b1v, c1, d1;
            up2(s0x, a0, b0v); up2(s0y, c0, d0);
            up2(s1x, a1, b1v); up2(s1y, c1, d1);
            float s0 = (a0 + b0v) + (c0 + d0);
            float s1 = (a1 + b1v) + (c1 + d1);
            up2(s2x, a0, b0v); up2(s2y, c0, d0);
            up2(s3x, a1, b1v); up2(s3y, c1, d1);
            float s2 = (a0 + b0v) + (c0 + d0);
            float s3 = (a1 + b1v) + (c1 + d1);
            s0 = (j + 0 < jmax) ? s0 : -1e30f;
            s1 = (j + 1 < jmax) ? s1 : -1e30f;
            s2 = (j + 2 < jmax) ? s2 : -1e30f;
            s3 = (j + 3 < jmax) ? s3 : -1e30f;
            myS[j + 0] = s0; myS[j + 1] = s1;
            myS[j + 2] = s2; myS[j + 3] = s3;
            tmax = fmaxf(tmax, fmaxf(fmaxf(s0, s1), fmaxf(s2, s3)));
        }

        float newm = fmaxf(mrun, tmax);
        float corr = __expf(mrun - newm);   // 0 when mrun == -inf
        lrun *= corr;
        ull c2 = pk2(corr, corr);
        #pragma unroll
        for (int kk = 0; kk < 32; kk++) acc2[kk] = mul2(acc2[kk], c2);

        // pass 2: p * V with packed FMAs (32 independent chains)
        for (int j = 0; j < jmax; j++) {
            float p = __expf(myS[j] - newm);
            lrun += p;
            ull p2 = pk2(p, p);
            const ull* vr = reinterpret_cast<const ull*>(&Vs[j * 64]);
            #pragma unroll
            for (int kk = 0; kk < 32; kk++)
                acc2[kk] = fma2(p2, vr[kk], acc2[kk]);
        }
        mrun = newm;
    }

    float inv = 1.0f / lrun;
    float* Orow = O + (size_t)(b * TLEN + q) * EMB + h * HDIM;
    #pragma unroll
    for (int kk = 0; kk < 32; kk++) {
        float lo, hi;
        up2(acc2[kk], lo, hi);
        reinterpret_cast<float2*>(Orow)[kk] = make_float2(lo * inv, hi * inv);
    }
}

// ---------------------------------------------------------------------------
// Launcher
// ---------------------------------------------------------------------------
extern "C" void kernel_launch(void* const* d_in, const int* in_sizes, int n_in,
                              void* d_out, int out_size)
{
    const float* x    = (const float*)d_in[0];
    const float* Wk   = (const float*)d_in[1];
    const float* Wq   = (const float*)d_in[2];
    const float* Wv   = (const float*)d_in[3];
    const float* Wu   = (const float*)d_in[4];
    const float* klnw = (const float*)d_in[5];
    const float* klnb = (const float*)d_in[6];
    const float* qlnw = (const float*)d_in[7];
    const float* qlnb = (const float*)d_in[8];
    float* out = (float*)d_out;

    float *Kp, *Qp, *Vp, *Ap;
    __half *xf, *af, *Wf;
    cudaGetSymbolAddress((void**)&Kp, g_K);
    cudaGetSymbolAddress((void**)&Qp, g_Q);
    cudaGetSymbolAddress((void**)&Vp, g_V);
    cudaGetSymbolAddress((void**)&Ap, g_A);
    cudaGetSymbolAddress((void**)&xf, g_xf);
    cudaGetSymbolAddress((void**)&af, g_af);
    cudaGetSymbolAddress((void**)&Wf, g_Wf);

    const int WN = EMB * EMB;

    // Conversions to fp16
    cvt_kernel<<<(MROWS * EMB / 4 + 255) / 256, 256>>>(x, xf, MROWS * EMB / 4);
    cvt_kernel<<<(WN / 4 + 255) / 256, 256>>>(Wk, Wf + 0 * WN, WN / 4);
    cvt_kernel<<<(WN / 4 + 255) / 256, 256>>>(Wq, Wf + 1 * WN, WN / 4);
    cvt_kernel<<<(WN / 4 + 255) / 256, 256>>>(Wv, Wf + 2 * WN, WN / 4);
    cvt_kernel<<<(WN / 4 + 255) / 256, 256>>>(Wu, Wf + 3 * WN, WN / 4);

    // QKV projections (tensor cores, single-pass fp16)
    cudaFuncSetAttribute(gemm_fp16_kernel,
                         cudaFuncAttributeMaxDynamicSharedMemorySize, GEMM_SMEM);
    dim3 ggrid(EMB / BN, MROWS / BM);
    gemm_fp16_kernel<<<ggrid, 256, GEMM_SMEM>>>(xf, Wf + 0 * WN, Kp, MROWS, EMB, EMB);
    gemm_fp16_kernel<<<ggrid, 256, GEMM_SMEM>>>(xf, Wf + 1 * WN, Qp, MROWS, EMB, EMB);
    gemm_fp16_kernel<<<ggrid, 256, GEMM_SMEM>>>(xf, Wf + 2 * WN, Vp, MROWS, EMB, EMB);

    // LayerNorms
    int rows = MROWS * HEADS;
    ln_kernel<<<rows / 8, 256>>>(Kp, klnw, klnb, rows);
    ln_kernel<<<rows / 8, 256>>>(Qp, qlnw, qlnb, rows);

    // Attention (packed f32x2)
    int smem = (4096 + 4096 + 64 * SSTRIDE) * (int)sizeof(float);
    cudaFuncSetAttribute(attn_kernel, cudaFuncAttributeMaxDynamicSharedMemorySize, smem);
    dim3 agrid(TLEN / 64, HEADS, BATCH);
    attn_kernel<<<agrid, 64, smem>>>(Qp, Kp, Vp, Ap);

    // Output projection
    cvt_kernel<<<(MROWS * EMB / 4 + 255) / 256, 256>>>(Ap, af, MROWS * EMB / 4);
    gemm_fp16_kernel<<<ggrid, 256, GEMM_SMEM>>>(af, Wf + 3 * WN, out, MROWS, EMB, EMB);
}

// round 11
// speedup vs baseline: 4.6523x; 4.6523x over previous
#include <cuda_runtime.h>
#include <cuda_fp16.h>
#include <math.h>
#include <stdint.h>

// Problem constants (fixed shapes)
#define BATCH 2
#define TLEN  2048
#define EMB   1024
#define HEADS 16
#define HDIM  64
#define MROWS (BATCH * TLEN)   // 4096
#define SCALE 0.125f           // 1/sqrt(64), exact power of two
#define LN_EPS 1e-5f

// Scratch (device globals — no allocation allowed)
__device__ float g_K[MROWS * EMB];
__device__ float g_Q[MROWS * EMB];
__device__ float g_V[MROWS * EMB];

__device__ __half g_xf[MROWS * EMB];
__device__ __half g_af[MROWS * EMB];
__device__ __half g_qh[MROWS * EMB];
__device__ __half g_kh[MROWS * EMB];
__device__ __half g_vh[MROWS * EMB];
__device__ __half g_Wf[4 * EMB * EMB];

// ---------------------------------------------------------------------------
// Helpers
// ---------------------------------------------------------------------------
__device__ __forceinline__ uint32_t s2u(const void* p) {
    return (uint32_t)__cvta_generic_to_shared(p);
}

__device__ __forceinline__ void cp_async16(uint32_t saddr, const void* gaddr) {
    asm volatile("cp.async.cg.shared.global [%0], [%1], 16;"
                 :: "r"(saddr), "l"(gaddr) : "memory");
}

__device__ __forceinline__ void ldsm_x4(uint32_t r[4], uint32_t addr) {
    asm volatile("ldmatrix.sync.aligned.m8n8.x4.shared.b16 {%0,%1,%2,%3}, [%4];"
        : "=r"(r[0]), "=r"(r[1]), "=r"(r[2]), "=r"(r[3]) : "r"(addr));
}

__device__ __forceinline__ void ldsm_x4_t(uint32_t r[4], uint32_t addr) {
    asm volatile("ldmatrix.sync.aligned.m8n8.x4.trans.shared.b16 {%0,%1,%2,%3}, [%4];"
        : "=r"(r[0]), "=r"(r[1]), "=r"(r[2]), "=r"(r[3]) : "r"(addr));
}

__device__ __forceinline__ void mma_fp16(float c[4], const uint32_t a[4],
                                         uint32_t b0, uint32_t b1) {
    asm volatile(
        "mma.sync.aligned.m16n8k16.row.col.f32.f16.f16.f32 "
        "{%0,%1,%2,%3}, {%4,%5,%6,%7}, {%8,%9}, {%0,%1,%2,%3};"
        : "+f"(c[0]), "+f"(c[1]), "+f"(c[2]), "+f"(c[3])
        : "r"(a[0]), "r"(a[1]), "r"(a[2]), "r"(a[3]), "r"(b0), "r"(b1));
}

__device__ __forceinline__ uint32_t ph2(float a, float b) {
    __half2 h = __floats2half2_rn(a, b);
    return *reinterpret_cast<uint32_t*>(&h);
}

// ---------------------------------------------------------------------------
// Convert fp32 -> fp16. 4 elems/thread.
// ---------------------------------------------------------------------------
__global__ void __launch_bounds__(256) cvt_kernel(
    const float* __restrict__ X, __half* __restrict__ Y, int n4)
{
    int i = blockIdx.x * blockDim.x + threadIdx.x;
    if (i >= n4) return;
    float4 v = reinterpret_cast<const float4*>(X)[i];
    union { __half h[4]; uint2 u; } H;
    H.h[0] = __float2half(v.x);
    H.h[1] = __float2half(v.y);
    H.h[2] = __float2half(v.z);
    H.h[3] = __float2half(v.w);
    reinterpret_cast<uint2*>(Y)[i] = H.u;
}

// ---------------------------------------------------------------------------
// Tensor-core NT GEMM, single-pass fp16, fp32 accum: C = A @ B^T.
// Block tile 128x128x32, 256 threads, warp tile 32x64, double-buffered.
// ---------------------------------------------------------------------------
#define BM 128
#define BN 128
#define BK 32
#define LDSW 40
#define STG_ELEMS (128 * LDSW)
#define STAGE_ELEMS (2 * STG_ELEMS)
#define GEMM_SMEM (2 * STAGE_ELEMS * 2)   // 40960 B

__global__ void __launch_bounds__(256, 2) gemm_fp16_kernel(
    const __half* __restrict__ A, const __half* __restrict__ B,
    float* __restrict__ C, int M, int N, int K)
{
    extern __shared__ __half smem[];

    const int tid  = threadIdx.x;
    const int m0   = blockIdx.y * BM;
    const int n0   = blockIdx.x * BN;
    const int w    = tid >> 5;
    const int lane = tid & 31;
    const int wm   = (w >> 1) * 32;
    const int wn   = (w & 1) * 64;
    const int arow = lane & 15;
    const int acol = (lane >> 4) * 8;

    float acc[2][8][4];
    #pragma unroll
    for (int mf = 0; mf < 2; mf++)
        #pragma unroll
        for (int nf = 0; nf < 8; nf++)
            #pragma unroll
            for (int r = 0; r < 4; r++) acc[mf][nf][r] = 0.0f;

    const int NK = K / BK;

    auto load_stage = [&](int kc, int s) {
        const int k0 = kc * BK;
        __half* base = smem + s * STAGE_ELEMS;
        const uint32_t sb = s2u(base);
        #pragma unroll
        for (int j = 0; j < 2; j++) {
            int u   = tid + j * 256;
            int row = u >> 2;
            int c   = (u & 3) * 8;
            uint32_t so = (uint32_t)(row * LDSW + c) * 2;
            size_t ga = (size_t)(m0 + row) * K + k0 + c;
            size_t gb = (size_t)(n0 + row) * K + k0 + c;
            cp_async16(sb + 0 * STG_ELEMS * 2 + so, A + ga);
            cp_async16(sb + 1 * STG_ELEMS * 2 + so, B + gb);
        }
        asm volatile("cp.async.commit_group;");
    };

    load_stage(0, 0);

    for (int kc = 0; kc < NK; kc++) {
        if (kc + 1 < NK) {
            load_stage(kc + 1, (kc + 1) & 1);
            asm volatile("cp.async.wait_group 1;" ::: "memory");
        } else {
            asm volatile("cp.async.wait_group 0;" ::: "memory");
        }
        __syncthreads();

        const int s = kc & 1;
        __half (*sA)[LDSW] =
            reinterpret_cast<__half(*)[LDSW]>(smem + s * STAGE_ELEMS);
        __half (*sB)[LDSW] =
            reinterpret_cast<__half(*)[LDSW]>(smem + s * STAGE_ELEMS + STG_ELEMS);

        #pragma unroll
        for (int kf = 0; kf < 2; kf++) {
            uint32_t af[2][4];
            #pragma unroll
            for (int mf = 0; mf < 2; mf++)
                ldsm_x4(af[mf], s2u(&sA[wm + mf * 16 + arow][kf * 16 + acol]));
            #pragma unroll
            for (int nb = 0; nb < 4; nb++) {
                uint32_t bf[4];
                ldsm_x4(bf, s2u(&sB[wn + nb * 16 + arow][kf * 16 + acol]));
                #pragma unroll
                for (int mf = 0; mf < 2; mf++) {
                    mma_fp16(acc[mf][2 * nb],     af[mf], bf[0], bf[2]);
                    mma_fp16(acc[mf][2 * nb + 1], af[mf], bf[1], bf[3]);
                }
            }
        }
        __syncthreads();
    }

    #pragma unroll
    for (int mf = 0; mf < 2; mf++) {
        int row = m0 + wm + mf * 16 + (lane >> 2);
        #pragma unroll
        for (int nf = 0; nf < 8; nf++) {
            int col = n0 + wn + nf * 8 + (lane & 3) * 2;
            *reinterpret_cast<float2*>(&C[(size_t)row * N + col]) =
                make_float2(acc[mf][nf][0], acc[mf][nf][1]);
            *reinterpret_cast<float2*>(&C[(size_t)(row + 8) * N + col]) =
                make_float2(acc[mf][nf][2], acc[mf][nf][3]);
        }
    }
}

// ---------------------------------------------------------------------------
// Per-head LayerNorm over last dim (64), fp32 in -> fp16 out (scaled).
// One warp per row.
// ---------------------------------------------------------------------------
__global__ void __launch_bounds__(256) ln_kernel(
    const float* __restrict__ X, __half* __restrict__ Y,
    const float* __restrict__ w, const float* __restrict__ bias,
    int rows, float oscale)
{
    int warp = (blockIdx.x * blockDim.x + threadIdx.x) >> 5;
    int lane = threadIdx.x & 31;
    if (warp >= rows) return;

    const float* r = X + (size_t)warp * HDIM;
    float v0 = r[lane];
    float v1 = r[lane + 32];

    float sum = v0 + v1;
    #pragma unroll
    for (int o = 16; o > 0; o >>= 1) sum += __shfl_xor_sync(0xffffffffu, sum, o);
    float mu = sum * (1.0f / 64.0f);

    float d0 = v0 - mu, d1 = v1 - mu;
    float sq = d0 * d0 + d1 * d1;
    #pragma unroll
    for (int o = 16; o > 0; o >>= 1) sq += __shfl_xor_sync(0xffffffffu, sq, o);
    float inv = rsqrtf(sq * (1.0f / 64.0f) + LN_EPS);

    __half* y = Y + (size_t)warp * HDIM;
    y[lane]      = __float2half((d0 * inv * w[lane]      + bias[lane])      * oscale);
    y[lane + 32] = __float2half((d1 * inv * w[lane + 32] + bias[lane + 32]) * oscale);
}

// ---------------------------------------------------------------------------
// FA2-style causal attention on tensor cores (fp16 in, fp16 out).
// 128 threads = 4 warps; block handles 64 q-rows; warp handles 16 rows.
// QK^T and PV both via mma.sync m16n8k16; register online softmax.
// O written as fp16 [b,t,e] directly (input of the output GEMM).
// ---------------------------------------------------------------------------
#define ASTRIDE 72

__global__ void __launch_bounds__(128) attn_kernel(
    const __half* __restrict__ Qh, const __half* __restrict__ Kh,
    const __half* __restrict__ Vh, __half* __restrict__ O)
{
    __shared__ __half sQ[64 * ASTRIDE];
    __shared__ __half sK[64 * ASTRIDE];
    __shared__ __half sV[64 * ASTRIDE];

    const int tid  = threadIdx.x;
    const int wid  = tid >> 5;
    const int lane = tid & 31;
    const int qb   = blockIdx.x;
    const int h    = blockIdx.y;
    const int b    = blockIdx.z;
    const int wm   = wid * 16;
    const int r0   = lane >> 2;          // row within 8-row half
    const int cq   = lane & 3;           // col pair within n8

    // Load Q tile (64x64 halfs; 512 16B units; 4 per thread)
    #pragma unroll
    for (int it = 0; it < 4; it++) {
        int u   = tid + it * 128;
        int row = u >> 3;
        int c8  = (u & 7) * 8;
        const __half* src =
            Qh + ((size_t)((b * TLEN + qb * 64 + row) * HEADS + h)) * HDIM + c8;
        *reinterpret_cast<uint4*>(&sQ[row * ASTRIDE + c8]) =
            *reinterpret_cast<const uint4*>(src);
    }

    float o[8][4];
    #pragma unroll
    for (int nf = 0; nf < 8; nf++)
        #pragma unroll
        for (int r = 0; r < 4; r++) o[nf][r] = 0.0f;
    float m0 = -INFINITY, m1 = -INFINITY, l0 = 0.0f, l1 = 0.0f;

    for (int j0 = 0; j0 <= qb * 64; j0 += 64) {
        __syncthreads();
        #pragma unroll
        for (int it = 0; it < 4; it++) {
            int u   = tid + it * 128;
            int row = u >> 3;
            int c8  = (u & 7) * 8;
            size_t gb = ((size_t)((b * TLEN + j0 + row) * HEADS + h)) * HDIM + c8;
            *reinterpret_cast<uint4*>(&sK[row * ASTRIDE + c8]) =
                *reinterpret_cast<const uint4*>(Kh + gb);
            *reinterpret_cast<uint4*>(&sV[row * ASTRIDE + c8]) =
                *reinterpret_cast<const uint4*>(Vh + gb);
        }
        __syncthreads();

        // S = Q_tile @ K_tile^T  (SCALE pre-folded into Q)
        float sc[8][4];
        #pragma unroll
        for (int nf = 0; nf < 8; nf++)
            #pragma unroll
            for (int r = 0; r < 4; r++) sc[nf][r] = 0.0f;

        #pragma unroll
        for (int kf = 0; kf < 4; kf++) {
            uint32_t a[4];
            ldsm_x4(a, s2u(&sQ[(wm + (lane & 15)) * ASTRIDE + kf * 16 + (lane >> 4) * 8]));
            #pragma unroll
            for (int nb = 0; nb < 4; nb++) {
                uint32_t bf[4];
                ldsm_x4(bf, s2u(&sK[(nb * 16 + (lane & 15)) * ASTRIDE + kf * 16 + (lane >> 4) * 8]));
                mma_fp16(sc[2 * nb],     a, bf[0], bf[2]);
                mma_fp16(sc[2 * nb + 1], a, bf[1], bf[3]);
            }
        }

        // Causal mask on the diagonal tile
        if (j0 == qb * 64) {
            int rl0 = wm + r0, rl1 = rl0 + 8;
            #pragma unroll
            for (int nf = 0; nf < 8; nf++) {
                int cc = 8 * nf + 2 * cq;
                if (cc     > rl0) sc[nf][0] = -1e30f;
                if (cc + 1 > rl0) sc[nf][1] = -1e30f;
                if (cc     > rl1) sc[nf][2] = -1e30f;
                if (cc + 1 > rl1) sc[nf][3] = -1e30f;
            }
        }

        // Online softmax (rows r=wm+r0 and r+8), quad-shuffle reductions
        float tm0 = -1e30f, tm1 = -1e30f;
        #pragma unroll
        for (int nf = 0; nf < 8; nf++) {
            tm0 = fmaxf(tm0, fmaxf(sc[nf][0], sc[nf][1]));
            tm1 = fmaxf(tm1, fmaxf(sc[nf][2], sc[nf][3]));
        }
        tm0 = fmaxf(tm0, __shfl_xor_sync(0xffffffffu, tm0, 1));
        tm0 = fmaxf(tm0, __shfl_xor_sync(0xffffffffu, tm0, 2));
        tm1 = fmaxf(tm1, __shfl_xor_sync(0xffffffffu, tm1, 1));
        tm1 = fmaxf(tm1, __shfl_xor_sync(0xffffffffu, tm1, 2));

        float nm0 = fmaxf(m0, tm0), nm1 = fmaxf(m1, tm1);
        float cor0 = __expf(m0 - nm0), cor1 = __expf(m1 - nm1);
        l0 *= cor0; l1 *= cor1;

        float rs0 = 0.0f, rs1 = 0.0f;
        uint32_t pA[8], pB[8];
        #pragma unroll
        for (int nf = 0; nf < 8; nf++) {
            float p0 = __expf(sc[nf][0] - nm0);
            float p1 = __expf(sc[nf][1] - nm0);
            float p2 = __expf(sc[nf][2] - nm1);
            float p3 = __expf(sc[nf][3] - nm1);
            rs0 += p0 + p1; rs1 += p2 + p3;
            pA[nf] = ph2(p0, p1);
            pB[nf] = ph2(p2, p3);
            o[nf][0] *= cor0; o[nf][1] *= cor0;
            o[nf][2] *= cor1; o[nf][3] *= cor1;
        }
        rs0 += __shfl_xor_sync(0xffffffffu, rs0, 1);
        rs0 += __shfl_xor_sync(0xffffffffu, rs0, 2);
        rs1 += __shfl_xor_sync(0xffffffffu, rs1, 1);
        rs1 += __shfl_xor_sync(0xffffffffu, rs1, 2);
        l0 += rs0; l1 += rs1;
        m0 = nm0; m1 = nm1;

        // O += P @ V_tile  (P from registers; V via trans-ldmatrix)
        #pragma unroll
        for (int j16 = 0; j16 < 4; j16++) {
            uint32_t pa[4] = {pA[2 * j16], pB[2 * j16], pA[2 * j16 + 1], pB[2 * j16 + 1]};
            #pragma unroll
            for (int db = 0; db < 4; db++) {
                uint32_t vb[4];
                ldsm_x4_t(vb, s2u(&sV[(j16 * 16 + (lane & 7) + (lane >> 4) * 8) * ASTRIDE
                                      + db * 16 + ((lane >> 3) & 1) * 8]));
                mma_fp16(o[2 * db],     pa, vb[0], vb[2]);
                mma_fp16(o[2 * db + 1], pa, vb[1], vb[3]);
            }
        }
    }

    // Normalize and store fp16 into [b,t,e]
    float li0 = 1.0f / l0, li1 = 1.0f / l1;
    int rg0 = qb * 64 + wm + r0;
    int rg1 = rg0 + 8;
    #pragma unroll
    for (int nf = 0; nf < 8; nf++) {
        int col = 8 * nf + 2 * cq;
        uint32_t v0 = ph2(o[nf][0] * li0, o[nf][1] * li0);
        uint32_t v1 = ph2(o[nf][2] * li1, o[nf][3] * li1);
        *reinterpret_cast<uint32_t*>(
            &O[(size_t)(b * TLEN + rg0) * EMB + h * HDIM + col]) = v0;
        *reinterpret_cast<uint32_t*>(
            &O[(size_t)(b * TLEN + rg1) * EMB + h * HDIM + col]) = v1;
    }
}

// ---------------------------------------------------------------------------
// Launcher
// ---------------------------------------------------------------------------
extern "C" void kernel_launch(void* const* d_in, const int* in_sizes, int n_in,
                              void* d_out, int out_size)
{
    const float* x    = (const float*)d_in[0];
    const float* Wk   = (const float*)d_in[1];
    const float* Wq   = (const float*)d_in[2];
    const float* Wv   = (const float*)d_in[3];
    const float* Wu   = (const float*)d_in[4];
    const float* klnw = (const float*)d_in[5];
    const float* klnb = (const float*)d_in[6];
    const float* qlnw = (const float*)d_in[7];
    const float* qlnb = (const float*)d_in[8];
    float* out = (float*)d_out;

    float *Kp, *Qp, *Vp;
    __half *xf, *af, *qh, *kh, *vh, *Wf;
    cudaGetSymbolAddress((void**)&Kp, g_K);
    cudaGetSymbolAddress((void**)&Qp, g_Q);
    cudaGetSymbolAddress((void**)&Vp, g_V);
    cudaGetSymbolAddress((void**)&xf, g_xf);
    cudaGetSymbolAddress((void**)&af, g_af);
    cudaGetSymbolAddress((void**)&qh, g_qh);
    cudaGetSymbolAddress((void**)&kh, g_kh);
    cudaGetSymbolAddress((void**)&vh, g_vh);
    cudaGetSymbolAddress((void**)&Wf, g_Wf);

    const int WN = EMB * EMB;

    // Conversions to fp16
    cvt_kernel<<<(MROWS * EMB / 4 + 255) / 256, 256>>>(x, xf, MROWS * EMB / 4);
    cvt_kernel<<<(WN / 4 + 255) / 256, 256>>>(Wk, Wf + 0 * WN, WN / 4);
    cvt_kernel<<<(WN / 4 + 255) / 256, 256>>>(Wq, Wf + 1 * WN, WN / 4);
    cvt_kernel<<<(WN / 4 + 255) / 256, 256>>>(Wv, Wf + 2 * WN, WN / 4);
    cvt_kernel<<<(WN / 4 + 255) / 256, 256>>>(Wu, Wf + 3 * WN, WN / 4);

    // QKV projections (tensor cores, single-pass fp16)
    cudaFuncSetAttribute(gemm_fp16_kernel,
                         cudaFuncAttributeMaxDynamicSharedMemorySize, GEMM_SMEM);
    dim3 ggrid(EMB / BN, MROWS / BM);
    gemm_fp16_kernel<<<ggrid, 256, GEMM_SMEM>>>(xf, Wf + 0 * WN, Kp, MROWS, EMB, EMB);
    gemm_fp16_kernel<<<ggrid, 256, GEMM_SMEM>>>(xf, Wf + 1 * WN, Qp, MROWS, EMB, EMB);
    gemm_fp16_kernel<<<ggrid, 256, GEMM_SMEM>>>(xf, Wf + 2 * WN, Vp, MROWS, EMB, EMB);

    // LayerNorms -> fp16 (SCALE folded into Q)
    int rows = MROWS * HEADS;
    ln_kernel<<<rows / 8, 256>>>(Kp, kh, klnw, klnb, rows, 1.0f);
    ln_kernel<<<rows / 8, 256>>>(Qp, qh, qlnw, qlnb, rows, SCALE);
    cvt_kernel<<<(MROWS * EMB / 4 + 255) / 256, 256>>>(Vp, vh, MROWS * EMB / 4);

    // Attention (tensor-core FA2), writes fp16 directly into af
    dim3 agrid(TLEN / 64, HEADS, BATCH);
    attn_kernel<<<agrid, 128>>>(qh, kh, vh, af);

    // Output projection
    gemm_fp16_kernel<<<ggrid, 256, GEMM_SMEM>>>(af, Wf + 3 * WN, out, MROWS, EMB, EMB);
}

// round 14
// speedup vs baseline: 4.9361x; 1.0610x over previous
#include <cuda_runtime.h>
#include <cuda_fp16.h>
#include <math.h>
#include <stdint.h>

// Problem constants (fixed shapes)
#define BATCH 2
#define TLEN  2048
#define EMB   1024
#define HEADS 16
#define HDIM  64
#define MROWS (BATCH * TLEN)   // 4096
#define SCALE 0.125f           // 1/sqrt(64), exact power of two
#define LN_EPS 1e-5f

// Scratch (device globals — no allocation allowed)
__device__ float g_K[MROWS * EMB];
__device__ float g_Q[MROWS * EMB];

__device__ __half g_xf[MROWS * EMB];
__device__ __half g_af[MROWS * EMB];
__device__ __half g_qh[MROWS * EMB];
__device__ __half g_kh[MROWS * EMB];
__device__ __half g_vh[MROWS * EMB];
__device__ __half g_Wf[4 * EMB * EMB];

// ---------------------------------------------------------------------------
// Helpers
// ---------------------------------------------------------------------------
__device__ __forceinline__ uint32_t s2u(const void* p) {
    return (uint32_t)__cvta_generic_to_shared(p);
}

__device__ __forceinline__ void cp_async16(uint32_t saddr, const void* gaddr) {
    asm volatile("cp.async.cg.shared.global [%0], [%1], 16;"
                 :: "r"(saddr), "l"(gaddr) : "memory");
}

__device__ __forceinline__ void ldsm_x4(uint32_t r[4], uint32_t addr) {
    asm volatile("ldmatrix.sync.aligned.m8n8.x4.shared.b16 {%0,%1,%2,%3}, [%4];"
        : "=r"(r[0]), "=r"(r[1]), "=r"(r[2]), "=r"(r[3]) : "r"(addr));
}

__device__ __forceinline__ void ldsm_x4_t(uint32_t r[4], uint32_t addr) {
    asm volatile("ldmatrix.sync.aligned.m8n8.x4.trans.shared.b16 {%0,%1,%2,%3}, [%4];"
        : "=r"(r[0]), "=r"(r[1]), "=r"(r[2]), "=r"(r[3]) : "r"(addr));
}

__device__ __forceinline__ void mma_fp16(float c[4], const uint32_t a[4],
                                         uint32_t b0, uint32_t b1) {
    asm volatile(
        "mma.sync.aligned.m16n8k16.row.col.f32.f16.f16.f32 "
        "{%0,%1,%2,%3}, {%4,%5,%6,%7}, {%8,%9}, {%0,%1,%2,%3};"
        : "+f"(c[0]), "+f"(c[1]), "+f"(c[2]), "+f"(c[3])
        : "r"(a[0]), "r"(a[1]), "r"(a[2]), "r"(a[3]), "r"(b0), "r"(b1));
}

__device__ __forceinline__ uint32_t ph2(float a, float b) {
    __half2 h = __floats2half2_rn(a, b);
    return *reinterpret_cast<uint32_t*>(&h);
}

// ---------------------------------------------------------------------------
// Convert fp32 -> fp16: x (single tensor)
// ---------------------------------------------------------------------------
__global__ void __launch_bounds__(256) cvt_kernel(
    const float* __restrict__ X, __half* __restrict__ Y, int n4)
{
    int i = blockIdx.x * blockDim.x + threadIdx.x;
    if (i >= n4) return;
    float4 v = reinterpret_cast<const float4*>(X)[i];
    union { __half h[4]; uint2 u; } H;
    H.h[0] = __float2half(v.x);
    H.h[1] = __float2half(v.y);
    H.h[2] = __float2half(v.z);
    H.h[3] = __float2half(v.w);
    reinterpret_cast<uint2*>(Y)[i] = H.u;
}

// Convert all 4 weight matrices in one launch (contiguous destination).
__global__ void __launch_bounds__(256) cvt_w_kernel(
    const float* __restrict__ W0, const float* __restrict__ W1,
    const float* __restrict__ W2, const float* __restrict__ W3,
    __half* __restrict__ Y)
{
    const int per = EMB * EMB / 4;     // 262144 float4 units per weight
    int u = blockIdx.x * blockDim.x + threadIdx.x;
    int wsel = u / per;
    int off  = u - wsel * per;
    const float* W = (wsel == 0) ? W0 : (wsel == 1) ? W1 : (wsel == 2) ? W2 : W3;
    float4 v = reinterpret_cast<const float4*>(W)[off];
    union { __half h[4]; uint2 uu; } H;
    H.h[0] = __float2half(v.x);
    H.h[1] = __float2half(v.y);
    H.h[2] = __float2half(v.z);
    H.h[3] = __float2half(v.w);
    reinterpret_cast<uint2*>(Y)[(size_t)wsel * per + off] = H.uu;
}

// ---------------------------------------------------------------------------
// GEMM core: block tile 128x128x32, 256 threads, warp tile 32x64,
// double-buffered cp.async. Shared by both GEMM kernels below.
// ---------------------------------------------------------------------------
#define BM 128
#define BN 128
#define BK 32
#define LDSW 40
#define STG_ELEMS (128 * LDSW)
#define STAGE_ELEMS (2 * STG_ELEMS)
#define GEMM_SMEM (2 * STAGE_ELEMS * 2)   // 40960 B

struct GemmAcc { float a[2][8][4]; };

__device__ __forceinline__ void gemm_core(
    const __half* __restrict__ A, const __half* __restrict__ B,
    int m0, int n0, int K, __half* smem, GemmAcc& R)
{
    const int tid  = threadIdx.x;
    const int w    = tid >> 5;
    const int lane = tid & 31;
    const int wm   = (w >> 1) * 32;
    const int wn   = (w & 1) * 64;
    const int arow = lane & 15;
    const int acol = (lane >> 4) * 8;

    #pragma unroll
    for (int mf = 0; mf < 2; mf++)
        #pragma unroll
        for (int nf = 0; nf < 8; nf++)
            #pragma unroll
            for (int r = 0; r < 4; r++) R.a[mf][nf][r] = 0.0f;

    const int NK = K / BK;

    auto load_stage = [&](int kc, int s) {
        const int k0 = kc * BK;
        const uint32_t sb = s2u(smem + s * STAGE_ELEMS);
        #pragma unroll
        for (int j = 0; j < 2; j++) {
            int u   = tid + j * 256;
            int row = u >> 2;
            int c   = (u & 3) * 8;
            uint32_t so = (uint32_t)(row * LDSW + c) * 2;
            size_t ga = (size_t)(m0 + row) * K + k0 + c;
            size_t gb = (size_t)(n0 + row) * K + k0 + c;
            cp_async16(sb + 0 * STG_ELEMS * 2 + so, A + ga);
            cp_async16(sb + 1 * STG_ELEMS * 2 + so, B + gb);
        }
        asm volatile("cp.async.commit_group;");
    };

    load_stage(0, 0);

    for (int kc = 0; kc < NK; kc++) {
        if (kc + 1 < NK) {
            load_stage(kc + 1, (kc + 1) & 1);
            asm volatile("cp.async.wait_group 1;" ::: "memory");
        } else {
            asm volatile("cp.async.wait_group 0;" ::: "memory");
        }
        __syncthreads();

        const int s = kc & 1;
        __half (*sA)[LDSW] = reinterpret_cast<__half(*)[LDSW]>(smem + s * STAGE_ELEMS);
        __half (*sB)[LDSW] = reinterpret_cast<__half(*)[LDSW]>(smem + s * STAGE_ELEMS + STG_ELEMS);

        #pragma unroll
        for (int kf = 0; kf < 2; kf++) {
            uint32_t af[2][4];
            #pragma unroll
            for (int mf = 0; mf < 2; mf++)
                ldsm_x4(af[mf], s2u(&sA[wm + mf * 16 + arow][kf * 16 + acol]));
            #pragma unroll
            for (int nb = 0; nb < 4; nb++) {
                uint32_t bf[4];
                ldsm_x4(bf, s2u(&sB[wn + nb * 16 + arow][kf * 16 + acol]));
                #pragma unroll
                for (int mf = 0; mf < 2; mf++) {
                    mma_fp16(R.a[mf][2 * nb],     af[mf], bf[0], bf[2]);
                    mma_fp16(R.a[mf][2 * nb + 1], af[mf], bf[1], bf[3]);
                }
            }
        }
        __syncthreads();
    }
}

// Plain fp32-output GEMM (used for the output projection): C[M,N] = A@B^T
__global__ void __launch_bounds__(256, 2) gemm_fp16_kernel(
    const __half* __restrict__ A, const __half* __restrict__ B,
    float* __restrict__ C, int M, int N, int K)
{
    extern __shared__ __half smem[];
    GemmAcc R;
    const int m0 = blockIdx.y * BM;
    const int n0 = blockIdx.x * BN;
    gemm_core(A, B, m0, n0, K, smem, R);

    const int w    = threadIdx.x >> 5;
    const int lane = threadIdx.x & 31;
    const int wm   = (w >> 1) * 32;
    const int wn   = (w & 1) * 64;
    #pragma unroll
    for (int mf = 0; mf < 2; mf++) {
        int row = m0 + wm + mf * 16 + (lane >> 2);
        #pragma unroll
        for (int nf = 0; nf < 8; nf++) {
            int col = n0 + wn + nf * 8 + (lane & 3) * 2;
            *reinterpret_cast<float2*>(&C[(size_t)row * N + col]) =
                make_float2(R.a[mf][nf][0], R.a[mf][nf][1]);
            *reinterpret_cast<float2*>(&C[(size_t)(row + 8) * N + col]) =
                make_float2(R.a[mf][nf][2], R.a[mf][nf][3]);
        }
    }
}

// Fused QKV GEMM: B = concatenated [Wk;Wq;Wv] (3072 x 1024).
// n-tile routes output: K -> fp32, Q -> fp32, V -> fp16 (direct attn input).
__global__ void __launch_bounds__(256, 2) gemm_qkv_kernel(
    const __half* __restrict__ A, const __half* __restrict__ B,
    float* __restrict__ Kp, float* __restrict__ Qp, __half* __restrict__ Vh)
{
    extern __shared__ __half smem[];
    GemmAcc R;
    const int m0 = blockIdx.y * BM;
    const int n0 = blockIdx.x * BN;          // 0..2944 within 3072
    gemm_core(A, B, m0, n0, EMB, smem, R);

    const int which = n0 >> 10;              // 0=K, 1=Q, 2=V
    const int nc    = n0 & 1023;             // column within the 1024-wide output
    const int w    = threadIdx.x >> 5;
    const int lane = threadIdx.x & 31;
    const int wm   = (w >> 1) * 32;
    const int wn   = (w & 1) * 64;

    if (which < 2) {
        float* C = (which == 0) ? Kp : Qp;
        #pragma unroll
        for (int mf = 0; mf < 2; mf++) {
            int row = m0 + wm + mf * 16 + (lane >> 2);
            #pragma unroll
            for (int nf = 0; nf < 8; nf++) {
                int col = nc + wn + nf * 8 + (lane & 3) * 2;
                *reinterpret_cast<float2*>(&C[(size_t)row * EMB + col]) =
                    make_float2(R.a[mf][nf][0], R.a[mf][nf][1]);
                *reinterpret_cast<float2*>(&C[(size_t)(row + 8) * EMB + col]) =
                    make_float2(R.a[mf][nf][2], R.a[mf][nf][3]);
            }
        }
    } else {
        #pragma unroll
        for (int mf = 0; mf < 2; mf++) {
            int row = m0 + wm + mf * 16 + (lane >> 2);
            #pragma unroll
            for (int nf = 0; nf < 8; nf++) {
                int col = nc + wn + nf * 8 + (lane & 3) * 2;
                *reinterpret_cast<uint32_t*>(&Vh[(size_t)row * EMB + col]) =
                    ph2(R.a[mf][nf][0], R.a[mf][nf][1]);
                *reinterpret_cast<uint32_t*>(&Vh[(size_t)(row + 8) * EMB + col]) =
                    ph2(R.a[mf][nf][2], R.a[mf][nf][3]);
            }
        }
    }
}

// ---------------------------------------------------------------------------
// Per-head LayerNorm over last dim (64), fp32 in -> fp16 out (scaled).
// ---------------------------------------------------------------------------
__global__ void __launch_bounds__(256) ln_kernel(
    const float* __restrict__ X, __half* __restrict__ Y,
    const float* __restrict__ w, const float* __restrict__ bias,
    int rows, float oscale)
{
    int warp = (blockIdx.x * blockDim.x + threadIdx.x) >> 5;
    int lane = threadIdx.x & 31;
    if (warp >= rows) return;

    const float* r = X + (size_t)warp * HDIM;
    float v0 = r[lane];
    float v1 = r[lane + 32];

    float sum = v0 + v1;
    #pragma unroll
    for (int o = 16; o > 0; o >>= 1) sum += __shfl_xor_sync(0xffffffffu, sum, o);
    float mu = sum * (1.0f / 64.0f);

    float d0 = v0 - mu, d1 = v1 - mu;
    float sq = d0 * d0 + d1 * d1;
    #pragma unroll
    for (int o = 16; o > 0; o >>= 1) sq += __shfl_xor_sync(0xffffffffu, sq, o);
    float inv = rsqrtf(sq * (1.0f / 64.0f) + LN_EPS);

    __half* y = Y + (size_t)warp * HDIM;
    y[lane]      = __float2half((d0 * inv * w[lane]      + bias[lane])      * oscale);
    y[lane + 32] = __float2half((d1 * inv * w[lane + 32] + bias[lane + 32]) * oscale);
}

// ---------------------------------------------------------------------------
// FA2-style causal attention on tensor cores (fp16 in, fp16 out).
// 128 threads = 4 warps; block handles 64 q-rows; warp handles 16 rows.
// ---------------------------------------------------------------------------
#define ASTRIDE 72

__global__ void __launch_bounds__(128) attn_kernel(
    const __half* __restrict__ Qh, const __half* __restrict__ Kh,
    const __half* __restrict__ Vh, __half* __restrict__ O)
{
    __shared__ __half sQ[64 * ASTRIDE];
    __shared__ __half sK[64 * ASTRIDE];
    __shared__ __half sV[64 * ASTRIDE];

    const int tid  = threadIdx.x;
    const int wid  = tid >> 5;
    const int lane = tid & 31;
    const int qb   = blockIdx.x;
    const int h    = blockIdx.y;
    const int b    = blockIdx.z;
    const int wm   = wid * 16;
    const int r0   = lane >> 2;
    const int cq   = lane & 3;

    #pragma unroll
    for (int it = 0; it < 4; it++) {
        int u   = tid + it * 128;
        int row = u >> 3;
        int c8  = (u & 7) * 8;
        const __half* src =
            Qh + ((size_t)((b * TLEN + qb * 64 + row) * HEADS + h)) * HDIM + c8;
        *reinterpret_cast<uint4*>(&sQ[row * ASTRIDE + c8]) =
            *reinterpret_cast<const uint4*>(src);
    }

    float o[8][4];
    #pragma unroll
    for (int nf = 0; nf < 8; nf++)
        #pragma unroll
        for (int r = 0; r < 4; r++) o[nf][r] = 0.0f;
    float m0 = -INFINITY, m1 = -INFINITY, l0 = 0.0f, l1 = 0.0f;

    for (int j0 = 0; j0 <= qb * 64; j0 += 64) {
        __syncthreads();
        #pragma unroll
        for (int it = 0; it < 4; it++) {
            int u   = tid + it * 128;
            int row = u >> 3;
            int c8  = (u & 7) * 8;
            size_t gb = ((size_t)((b * TLEN + j0 + row) * HEADS + h)) * HDIM + c8;
            *reinterpret_cast<uint4*>(&sK[row * ASTRIDE + c8]) =
                *reinterpret_cast<const uint4*>(Kh + gb);
            *reinterpret_cast<uint4*>(&sV[row * ASTRIDE + c8]) =
                *reinterpret_cast<const uint4*>(Vh + gb);
        }
        __syncthreads();

        float sc[8][4];
        #pragma unroll
        for (int nf = 0; nf < 8; nf++)
            #pragma unroll
            for (int r = 0; r < 4; r++) sc[nf][r] = 0.0f;

        #pragma unroll
        for (int kf = 0; kf < 4; kf++) {
            uint32_t a[4];
            ldsm_x4(a, s2u(&sQ[(wm + (lane & 15)) * ASTRIDE + kf * 16 + (lane >> 4) * 8]));
            #pragma unroll
            for (int nb = 0; nb < 4; nb++) {
                uint32_t bf[4];
                ldsm_x4(bf, s2u(&sK[(nb * 16 + (lane & 15)) * ASTRIDE + kf * 16 + (lane >> 4) * 8]));
                mma_fp16(sc[2 * nb],     a, bf[0], bf[2]);
                mma_fp16(sc[2 * nb + 1], a, bf[1], bf[3]);
            }
        }

        if (j0 == qb * 64) {
            int rl0 = wm + r0, rl1 = rl0 + 8;
            #pragma unroll
            for (int nf = 0; nf < 8; nf++) {
                int cc = 8 * nf + 2 * cq;
                if (cc     > rl0) sc[nf][0] = -1e30f;
                if (cc + 1 > rl0) sc[nf][1] = -1e30f;
                if (cc     > rl1) sc[nf][2] = -1e30f;
                if (cc + 1 > rl1) sc[nf][3] = -1e30f;
            }
        }

        float tm0 = -1e30f, tm1 = -1e30f;
        #pragma unroll
        for (int nf = 0; nf < 8; nf++) {
            tm0 = fmaxf(tm0, fmaxf(sc[nf][0], sc[nf][1]));
            tm1 = fmaxf(tm1, fmaxf(sc[nf][2], sc[nf][3]));
        }
        tm0 = fmaxf(tm0, __shfl_xor_sync(0xffffffffu, tm0, 1));
        tm0 = fmaxf(tm0, __shfl_xor_sync(0xffffffffu, tm0, 2));
        tm1 = fmaxf(tm1, __shfl_xor_sync(0xffffffffu, tm1, 1));
        tm1 = fmaxf(tm1, __shfl_xor_sync(0xffffffffu, tm1, 2));

        float nm0 = fmaxf(m0, tm0), nm1 = fmaxf(m1, tm1);
        float cor0 = __expf(m0 - nm0), cor1 = __expf(m1 - nm1);
        l0 *= cor0; l1 *= cor1;

        float rs0 = 0.0f, rs1 = 0.0f;
        uint32_t pA[8], pB[8];
        #pragma unroll
        for (int nf = 0; nf < 8; nf++) {
            float p0 = __expf(sc[nf][0] - nm0);
            float p1 = __expf(sc[nf][1] - nm0);
            float p2 = __expf(sc[nf][2] - nm1);
            float p3 = __expf(sc[nf][3] - nm1);
            rs0 += p0 + p1; rs1 += p2 + p3;
            pA[nf] = ph2(p0, p1);
            pB[nf] = ph2(p2, p3);
            o[nf][0] *= cor0; o[nf][1] *= cor0;
            o[nf][2] *= cor1; o[nf][3] *= cor1;
        }
        rs0 += __shfl_xor_sync(0xffffffffu, rs0, 1);
        rs0 += __shfl_xor_sync(0xffffffffu, rs0, 2);
        rs1 += __shfl_xor_sync(0xffffffffu, rs1, 1);
        rs1 += __shfl_xor_sync(0xffffffffu, rs1, 2);
        l0 += rs0; l1 += rs1;
        m0 = nm0; m1 = nm1;

        #pragma unroll
        for (int j16 = 0; j16 < 4; j16++) {
            uint32_t pa[4] = {pA[2 * j16], pB[2 * j16], pA[2 * j16 + 1], pB[2 * j16 + 1]};
            #pragma unroll
            for (int db = 0; db < 4; db++) {
                uint32_t vb[4];
                ldsm_x4_t(vb, s2u(&sV[(j16 * 16 + (lane & 7) + (lane >> 4) * 8) * ASTRIDE
                                      + db * 16 + ((lane >> 3) & 1) * 8]));
                mma_fp16(o[2 * db],     pa, vb[0], vb[2]);
                mma_fp16(o[2 * db + 1], pa, vb[1], vb[3]);
            }
        }
    }

    float li0 = 1.0f / l0, li1 = 1.0f / l1;
    int rg0 = qb * 64 + wm + r0;
    int rg1 = rg0 + 8;
    #pragma unroll
    for (int nf = 0; nf < 8; nf++) {
        int col = 8 * nf + 2 * cq;
        uint32_t v0 = ph2(o[nf][0] * li0, o[nf][1] * li0);
        uint32_t v1 = ph2(o[nf][2] * li1, o[nf][3] * li1);
        *reinterpret_cast<uint32_t*>(
            &O[(size_t)(b * TLEN + rg0) * EMB + h * HDIM + col]) = v0;
        *reinterpret_cast<uint32_t*>(
            &O[(size_t)(b * TLEN + rg1) * EMB + h * HDIM + col]) = v1;
    }
}

// ---------------------------------------------------------------------------
// Launcher
// ---------------------------------------------------------------------------
extern "C" void kernel_launch(void* const* d_in, const int* in_sizes, int n_in,
                              void* d_out, int out_size)
{
    const float* x    = (const float*)d_in[0];
    const float* Wk   = (const float*)d_in[1];
    const float* Wq   = (const float*)d_in[2];
    const float* Wv   = (const float*)d_in[3];
    const float* Wu   = (const float*)d_in[4];
    const float* klnw = (const float*)d_in[5];
    const float* klnb = (const float*)d_in[6];
    const float* qlnw = (const float*)d_in[7];
    const float* qlnb = (const float*)d_in[8];
    float* out = (float*)d_out;

    float *Kp, *Qp;
    __half *xf, *af, *qh, *kh, *vh, *Wf;
    cudaGetSymbolAddress((void**)&Kp, g_K);
    cudaGetSymbolAddress((void**)&Qp, g_Q);
    cudaGetSymbolAddress((void**)&xf, g_xf);
    cudaGetSymbolAddress((void**)&af, g_af);
    cudaGetSymbolAddress((void**)&qh, g_qh);
    cudaGetSymbolAddress((void**)&kh, g_kh);
    cudaGetSymbolAddress((void**)&vh, g_vh);
    cudaGetSymbolAddress((void**)&Wf, g_Wf);

    const int WN = EMB * EMB;

    // Conversions: x (1 launch) + all 4 weights (1 launch)
    cvt_kernel<<<(MROWS * EMB / 4 + 255) / 256, 256>>>(x, xf, MROWS * EMB / 4);
    cvt_w_kernel<<<(4 * WN / 4) / 256, 256>>>(Wk, Wq, Wv, Wu, Wf);

    // Fused QKV projection (N = 3072; V written as fp16 directly)
    cudaFuncSetAttribute(gemm_qkv_kernel,
                         cudaFuncAttributeMaxDynamicSharedMemorySize, GEMM_SMEM);
    cudaFuncSetAttribute(gemm_fp16_kernel,
                         cudaFuncAttributeMaxDynamicSharedMemorySize, GEMM_SMEM);
    dim3 qkvgrid(3 * EMB / BN, MROWS / BM);
    gemm_qkv_kernel<<<qkvgrid, 256, GEMM_SMEM>>>(xf, Wf, Kp, Qp, vh);

    // LayerNorms -> fp16 (SCALE folded into Q)
    int rows = MROWS * HEADS;
    ln_kernel<<<rows / 8, 256>>>(Kp, kh, klnw, klnb, rows, 1.0f);
    ln_kernel<<<rows / 8, 256>>>(Qp, qh, qlnw, qlnb, rows, SCALE);

    // Attention (tensor-core FA2), writes fp16 directly into af
    dim3 agrid(TLEN / 64, HEADS, BATCH);
    attn_kernel<<<agrid, 128>>>(qh, kh, vh, af);

    // Output projection
    dim3 ogrid(EMB / BN, MROWS / BM);
    gemm_fp16_kernel<<<ogrid, 256, GEMM_SMEM>>>(af, Wf + 3 * WN, out, MROWS, EMB, EMB);
}

// round 15
// speedup vs baseline: 5.2842x; 1.0705x over previous
#include <cuda_runtime.h>
#include <cuda_fp16.h>
#include <math.h>
#include <stdint.h>

// Problem constants (fixed shapes)
#define BATCH 2
#define TLEN  2048
#define EMB   1024
#define HEADS 16
#define HDIM  64
#define MROWS (BATCH * TLEN)   // 4096
#define SCALE 0.125f           // 1/sqrt(64), exact power of two
#define LN_EPS 1e-5f

// Scratch (device globals — no allocation allowed)
__device__ __half g_xf[MROWS * EMB];
__device__ __half g_af[MROWS * EMB];
__device__ __half g_qh[MROWS * EMB];
__device__ __half g_kh[MROWS * EMB];
__device__ __half g_vh[MROWS * EMB];
__device__ __half g_Wf[4 * EMB * EMB];

// ---------------------------------------------------------------------------
// Helpers
// ---------------------------------------------------------------------------
__device__ __forceinline__ uint32_t s2u(const void* p) {
    return (uint32_t)__cvta_generic_to_shared(p);
}

__device__ __forceinline__ void cp_async16(uint32_t saddr, const void* gaddr) {
    asm volatile("cp.async.cg.shared.global [%0], [%1], 16;"
                 :: "r"(saddr), "l"(gaddr) : "memory");
}

__device__ __forceinline__ void ldsm_x4(uint32_t r[4], uint32_t addr) {
    asm volatile("ldmatrix.sync.aligned.m8n8.x4.shared.b16 {%0,%1,%2,%3}, [%4];"
        : "=r"(r[0]), "=r"(r[1]), "=r"(r[2]), "=r"(r[3]) : "r"(addr));
}

__device__ __forceinline__ void ldsm_x4_t(uint32_t r[4], uint32_t addr) {
    asm volatile("ldmatrix.sync.aligned.m8n8.x4.trans.shared.b16 {%0,%1,%2,%3}, [%4];"
        : "=r"(r[0]), "=r"(r[1]), "=r"(r[2]), "=r"(r[3]) : "r"(addr));
}

__device__ __forceinline__ void mma_fp16(float c[4], const uint32_t a[4],
                                         uint32_t b0, uint32_t b1) {
    asm volatile(
        "mma.sync.aligned.m16n8k16.row.col.f32.f16.f16.f32 "
        "{%0,%1,%2,%3}, {%4,%5,%6,%7}, {%8,%9}, {%0,%1,%2,%3};"
        : "+f"(c[0]), "+f"(c[1]), "+f"(c[2]), "+f"(c[3])
        : "r"(a[0]), "r"(a[1]), "r"(a[2]), "r"(a[3]), "r"(b0), "r"(b1));
}

__device__ __forceinline__ uint32_t ph2(float a, float b) {
    __half2 h = __floats2half2_rn(a, b);
    return *reinterpret_cast<uint32_t*>(&h);
}

// ---------------------------------------------------------------------------
// Convert fp32 -> fp16: x (single tensor)
// ---------------------------------------------------------------------------
__global__ void __launch_bounds__(256) cvt_kernel(
    const float* __restrict__ X, __half* __restrict__ Y, int n4)
{
    int i = blockIdx.x * blockDim.x + threadIdx.x;
    if (i >= n4) return;
    float4 v = reinterpret_cast<const float4*>(X)[i];
    union { __half h[4]; uint2 u; } H;
    H.h[0] = __float2half(v.x);
    H.h[1] = __float2half(v.y);
    H.h[2] = __float2half(v.z);
    H.h[3] = __float2half(v.w);
    reinterpret_cast<uint2*>(Y)[i] = H.u;
}

// Convert all 4 weight matrices in one launch (contiguous destination).
__global__ void __launch_bounds__(256) cvt_w_kernel(
    const float* __restrict__ W0, const float* __restrict__ W1,
    const float* __restrict__ W2, const float* __restrict__ W3,
    __half* __restrict__ Y)
{
    const int per = EMB * EMB / 4;
    int u = blockIdx.x * blockDim.x + threadIdx.x;
    int wsel = u / per;
    int off  = u - wsel * per;
    const float* W = (wsel == 0) ? W0 : (wsel == 1) ? W1 : (wsel == 2) ? W2 : W3;
    float4 v = reinterpret_cast<const float4*>(W)[off];
    union { __half h[4]; uint2 uu; } H;
    H.h[0] = __float2half(v.x);
    H.h[1] = __float2half(v.y);
    H.h[2] = __float2half(v.z);
    H.h[3] = __float2half(v.w);
    reinterpret_cast<uint2*>(Y)[(size_t)wsel * per + off] = H.uu;
}

// ---------------------------------------------------------------------------
// GEMM core: block tile 128x128x32, 256 threads, warp tile 32x64,
// double-buffered cp.async.
// ---------------------------------------------------------------------------
#define BM 128
#define BN 128
#define BK 32
#define LDSW 40
#define STG_ELEMS (128 * LDSW)
#define STAGE_ELEMS (2 * STG_ELEMS)
#define GEMM_SMEM (2 * STAGE_ELEMS * 2)   // 40960 B

struct GemmAcc { float a[2][8][4]; };

__device__ __forceinline__ void gemm_core(
    const __half* __restrict__ A, const __half* __restrict__ B,
    int m0, int n0, int K, __half* smem, GemmAcc& R)
{
    const int tid  = threadIdx.x;
    const int w    = tid >> 5;
    const int lane = tid & 31;
    const int wm   = (w >> 1) * 32;
    const int wn   = (w & 1) * 64;
    const int arow = lane & 15;
    const int acol = (lane >> 4) * 8;

    #pragma unroll
    for (int mf = 0; mf < 2; mf++)
        #pragma unroll
        for (int nf = 0; nf < 8; nf++)
            #pragma unroll
            for (int r = 0; r < 4; r++) R.a[mf][nf][r] = 0.0f;

    const int NK = K / BK;

    auto load_stage = [&](int kc, int s) {
        const int k0 = kc * BK;
        const uint32_t sb = s2u(smem + s * STAGE_ELEMS);
        #pragma unroll
        for (int j = 0; j < 2; j++) {
            int u   = tid + j * 256;
            int row = u >> 2;
            int c   = (u & 3) * 8;
            uint32_t so = (uint32_t)(row * LDSW + c) * 2;
            size_t ga = (size_t)(m0 + row) * K + k0 + c;
            size_t gb = (size_t)(n0 + row) * K + k0 + c;
            cp_async16(sb + 0 * STG_ELEMS * 2 + so, A + ga);
            cp_async16(sb + 1 * STG_ELEMS * 2 + so, B + gb);
        }
        asm volatile("cp.async.commit_group;");
    };

    load_stage(0, 0);

    for (int kc = 0; kc < NK; kc++) {
        if (kc + 1 < NK) {
            load_stage(kc + 1, (kc + 1) & 1);
            asm volatile("cp.async.wait_group 1;" ::: "memory");
        } else {
            asm volatile("cp.async.wait_group 0;" ::: "memory");
        }
        __syncthreads();

        const int s = kc & 1;
        __half (*sA)[LDSW] = reinterpret_cast<__half(*)[LDSW]>(smem + s * STAGE_ELEMS);
        __half (*sB)[LDSW] = reinterpret_cast<__half(*)[LDSW]>(smem + s * STAGE_ELEMS + STG_ELEMS);

        #pragma unroll
        for (int kf = 0; kf < 2; kf++) {
            uint32_t af[2][4];
            #pragma unroll
            for (int mf = 0; mf < 2; mf++)
                ldsm_x4(af[mf], s2u(&sA[wm + mf * 16 + arow][kf * 16 + acol]));
            #pragma unroll
            for (int nb = 0; nb < 4; nb++) {
                uint32_t bf[4];
                ldsm_x4(bf, s2u(&sB[wn + nb * 16 + arow][kf * 16 + acol]));
                #pragma unroll
                for (int mf = 0; mf < 2; mf++) {
                    mma_fp16(R.a[mf][2 * nb],     af[mf], bf[0], bf[2]);
                    mma_fp16(R.a[mf][2 * nb + 1], af[mf], bf[1], bf[3]);
                }
            }
        }
        __syncthreads();
    }
}

// Plain fp32-output GEMM (used for the output projection): C[M,N] = A@B^T
__global__ void __launch_bounds__(256, 2) gemm_fp16_kernel(
    const __half* __restrict__ A, const __half* __restrict__ B,
    float* __restrict__ C, int M, int N, int K)
{
    extern __shared__ __half smem[];
    GemmAcc R;
    const int m0 = blockIdx.y * BM;
    const int n0 = blockIdx.x * BN;
    gemm_core(A, B, m0, n0, K, smem, R);

    const int w    = threadIdx.x >> 5;
    const int lane = threadIdx.x & 31;
    const int wm   = (w >> 1) * 32;
    const int wn   = (w & 1) * 64;
    #pragma unroll
    for (int mf = 0; mf < 2; mf++) {
        int row = m0 + wm + mf * 16 + (lane >> 2);
        #pragma unroll
        for (int nf = 0; nf < 8; nf++) {
            int col = n0 + wn + nf * 8 + (lane & 3) * 2;
            *reinterpret_cast<float2*>(&C[(size_t)row * N + col]) =
                make_float2(R.a[mf][nf][0], R.a[mf][nf][1]);
            *reinterpret_cast<float2*>(&C[(size_t)(row + 8) * N + col]) =
                make_float2(R.a[mf][nf][2], R.a[mf][nf][3]);
        }
    }
}

// Fused QKV GEMM + per-head LayerNorm epilogue.
// B = [Wk;Wq;Wv] (3072 x 1024). Each warp's 64-col block == one head vector,
// so LN(K), LN(Q) reduce entirely in registers (quad shuffles).
// Outputs all fp16: kh (LN), qh (LN*SCALE), vh (plain).
__global__ void __launch_bounds__(256, 2) gemm_qkv_kernel(
    const __half* __restrict__ A, const __half* __restrict__ B,
    __half* __restrict__ Kh, __half* __restrict__ Qh, __half* __restrict__ Vh,
    const float* __restrict__ klnw, const float* __restrict__ klnb,
    const float* __restrict__ qlnw, const float* __restrict__ qlnb)
{
    extern __shared__ __half smem[];
    GemmAcc R;
    const int m0 = blockIdx.y * BM;
    const int n0 = blockIdx.x * BN;          // 0..2944 within 3072
    gemm_core(A, B, m0, n0, EMB, smem, R);

    const int which = n0 >> 10;              // 0=K, 1=Q, 2=V
    const int nc    = n0 & 1023;
    const int w     = threadIdx.x >> 5;
    const int lane  = threadIdx.x & 31;
    const int wm    = (w >> 1) * 32;
    const int wn    = (w & 1) * 64;
    const int cq    = lane & 3;

    if (which == 2) {
        #pragma unroll
        for (int mf = 0; mf < 2; mf++) {
            int row = m0 + wm + mf * 16 + (lane >> 2);
            #pragma unroll
            for (int nf = 0; nf < 8; nf++) {
                int col = nc + wn + nf * 8 + cq * 2;
                *reinterpret_cast<uint32_t*>(&Vh[(size_t)row * EMB + col]) =
                    ph2(R.a[mf][nf][0], R.a[mf][nf][1]);
                *reinterpret_cast<uint32_t*>(&Vh[(size_t)(row + 8) * EMB + col]) =
                    ph2(R.a[mf][nf][2], R.a[mf][nf][3]);
            }
        }
        return;
    }

    // K or Q: fused LayerNorm over the 64-col head vector.
    const float* lw = (which == 0) ? klnw : qlnw;
    const float* lb = (which == 0) ? klnb : qlnb;
    const float oscale = (which == 0) ? 1.0f : SCALE;
    __half* Y = (which == 0) ? Kh : Qh;

    // Per-lane LN weights for its 16 columns (head col = nf*8 + cq*2)
    float wv[16], bv[16];
    #pragma unroll
    for (int nf = 0; nf < 8; nf++) {
        int c = nf * 8 + cq * 2;
        wv[2 * nf]     = lw[c];     wv[2 * nf + 1] = lw[c + 1];
        bv[2 * nf]     = lb[c];     bv[2 * nf + 1] = lb[c + 1];
    }

    #pragma unroll
    for (int mf = 0; mf < 2; mf++) {
        #pragma unroll
        for (int hh = 0; hh < 2; hh++) {      // row (hh=0) and row+8 (hh=1)
            // mean over 64 values: 16 per lane, 4 lanes per row
            float s = 0.0f;
            #pragma unroll
            for (int nf = 0; nf < 8; nf++)
                s += R.a[mf][nf][2 * hh] + R.a[mf][nf][2 * hh + 1];
            s += __shfl_xor_sync(0xffffffffu, s, 1);
            s += __shfl_xor_sync(0xffffffffu, s, 2);
            float mu = s * (1.0f / 64.0f);

            float sq = 0.0f;
            float d[16];
            #pragma unroll
            for (int nf = 0; nf < 8; nf++) {
                float d0 = R.a[mf][nf][2 * hh]     - mu;
                float d1 = R.a[mf][nf][2 * hh + 1] - mu;
                d[2 * nf] = d0; d[2 * nf + 1] = d1;
                sq += d0 * d0 + d1 * d1;
            }
            sq += __shfl_xor_sync(0xffffffffu, sq, 1);
            sq += __shfl_xor_sync(0xffffffffu, sq, 2);
            float inv = rsqrtf(sq * (1.0f / 64.0f) + LN_EPS);

            int row = m0 + wm + mf * 16 + (lane >> 2) + hh * 8;
            #pragma unroll
            for (int nf = 0; nf < 8; nf++) {
                int col = nc + wn + nf * 8 + cq * 2;
                float y0 = (d[2 * nf]     * inv * wv[2 * nf]     + bv[2 * nf])     * oscale;
                float y1 = (d[2 * nf + 1] * inv * wv[2 * nf + 1] + bv[2 * nf + 1]) * oscale;
                *reinterpret_cast<uint32_t*>(&Y[(size_t)row * EMB + col]) = ph2(y0, y1);
            }
        }
    }
}

// ---------------------------------------------------------------------------
// FA2-style causal attention on tensor cores (fp16 in, fp16 out).
// 128 threads = 4 warps; block handles 64 q-rows; warp handles 16 rows.
// ---------------------------------------------------------------------------
#define ASTRIDE 72

__global__ void __launch_bounds__(128) attn_kernel(
    const __half* __restrict__ Qh, const __half* __restrict__ Kh,
    const __half* __restrict__ Vh, __half* __restrict__ O)
{
    __shared__ __half sQ[64 * ASTRIDE];
    __shared__ __half sK[64 * ASTRIDE];
    __shared__ __half sV[64 * ASTRIDE];

    const int tid  = threadIdx.x;
    const int wid  = tid >> 5;
    const int lane = tid & 31;
    const int qb   = blockIdx.x;
    const int h    = blockIdx.y;
    const int b    = blockIdx.z;
    const int wm   = wid * 16;
    const int r0   = lane >> 2;
    const int cq   = lane & 3;

    #pragma unroll
    for (int it = 0; it < 4; it++) {
        int u   = tid + it * 128;
        int row = u >> 3;
        int c8  = (u & 7) * 8;
        const __half* src =
            Qh + ((size_t)((b * TLEN + qb * 64 + row) * HEADS + h)) * HDIM + c8;
        *reinterpret_cast<uint4*>(&sQ[row * ASTRIDE + c8]) =
            *reinterpret_cast<const uint4*>(src);
    }

    float o[8][4];
    #pragma unroll
    for (int nf = 0; nf < 8; nf++)
        #pragma unroll
        for (int r = 0; r < 4; r++) o[nf][r] = 0.0f;
    float m0 = -INFINITY, m1 = -INFINITY, l0 = 0.0f, l1 = 0.0f;

    for (int j0 = 0; j0 <= qb * 64; j0 += 64) {
        __syncthreads();
        #pragma unroll
        for (int it = 0; it < 4; it++) {
            int u   = tid + it * 128;
            int row = u >> 3;
            int c8  = (u & 7) * 8;
            size_t gb = ((size_t)((b * TLEN + j0 + row) * HEADS + h)) * HDIM + c8;
            *reinterpret_cast<uint4*>(&sK[row * ASTRIDE + c8]) =
                *reinterpret_cast<const uint4*>(Kh + gb);
            *reinterpret_cast<uint4*>(&sV[row * ASTRIDE + c8]) =
                *reinterpret_cast<const uint4*>(Vh + gb);
        }
        __syncthreads();

        float sc[8][4];
        #pragma unroll
        for (int nf = 0; nf < 8; nf++)
            #pragma unroll
            for (int r = 0; r < 4; r++) sc[nf][r] = 0.0f;

        #pragma unroll
        for (int kf = 0; kf < 4; kf++) {
            uint32_t a[4];
            ldsm_x4(a, s2u(&sQ[(wm + (lane & 15)) * ASTRIDE + kf * 16 + (lane >> 4) * 8]));
            #pragma unroll
            for (int nb = 0; nb < 4; nb++) {
                uint32_t bf[4];
                ldsm_x4(bf, s2u(&sK[(nb * 16 + (lane & 15)) * ASTRIDE + kf * 16 + (lane >> 4) * 8]));
                mma_fp16(sc[2 * nb],     a, bf[0], bf[2]);
                mma_fp16(sc[2 * nb + 1], a, bf[1], bf[3]);
            }
        }

        if (j0 == qb * 64) {
            int rl0 = wm + r0, rl1 = rl0 + 8;
            #pragma unroll
            for (int nf = 0; nf < 8; nf++) {
                int cc = 8 * nf + 2 * cq;
                if (cc     > rl0) sc[nf][0] = -1e30f;
                if (cc + 1 > rl0) sc[nf][1] = -1e30f;
                if (cc     > rl1) sc[nf][2] = -1e30f;
                if (cc + 1 > rl1) sc[nf][3] = -1e30f;
            }
        }

        float tm0 = -1e30f, tm1 = -1e30f;
        #pragma unroll
        for (int nf = 0; nf < 8; nf++) {
            tm0 = fmaxf(tm0, fmaxf(sc[nf][0], sc[nf][1]));
            tm1 = fmaxf(tm1, fmaxf(sc[nf][2], sc[nf][3]));
        }
        tm0 = fmaxf(tm0, __shfl_xor_sync(0xffffffffu, tm0, 1));
        tm0 = fmaxf(tm0, __shfl_xor_sync(0xffffffffu, tm0, 2));
        tm1 = fmaxf(tm1, __shfl_xor_sync(0xffffffffu, tm1, 1));
        tm1 = fmaxf(tm1, __shfl_xor_sync(0xffffffffu, tm1, 2));

        float nm0 = fmaxf(m0, tm0), nm1 = fmaxf(m1, tm1);
        float cor0 = __expf(m0 - nm0), cor1 = __expf(m1 - nm1);
        l0 *= cor0; l1 *= cor1;

        float rs0 = 0.0f, rs1 = 0.0f;
        uint32_t pA[8], pB[8];
        #pragma unroll
        for (int nf = 0; nf < 8; nf++) {
            float p0 = __expf(sc[nf][0] - nm0);
            float p1 = __expf(sc[nf][1] - nm0);
            float p2 = __expf(sc[nf][2] - nm1);
            float p3 = __expf(sc[nf][3] - nm1);
            rs0 += p0 + p1; rs1 += p2 + p3;
            pA[nf] = ph2(p0, p1);
            pB[nf] = ph2(p2, p3);
            o[nf][0] *= cor0; o[nf][1] *= cor0;
            o[nf][2] *= cor1; o[nf][3] *= cor1;
        }
        rs0 += __shfl_xor_sync(0xffffffffu, rs0, 1);
        rs0 += __shfl_xor_sync(0xffffffffu, rs0, 2);
        rs1 += __shfl_xor_sync(0xffffffffu, rs1, 1);
        rs1 += __shfl_xor_sync(0xffffffffu, rs1, 2);
        l0 += rs0; l1 += rs1;
        m0 = nm0; m1 = nm1;

        #pragma unroll
        for (int j16 = 0; j16 < 4; j16++) {
            uint32_t pa[4] = {pA[2 * j16], pB[2 * j16], pA[2 * j16 + 1], pB[2 * j16 + 1]};
            #pragma unroll
            for (int db = 0; db < 4; db++) {
                uint32_t vb[4];
                ldsm_x4_t(vb, s2u(&sV[(j16 * 16 + (lane & 7) + (lane >> 4) * 8) * ASTRIDE
                                      + db * 16 + ((lane >> 3) & 1) * 8]));
                mma_fp16(o[2 * db],     pa, vb[0], vb[2]);
                mma_fp16(o[2 * db + 1], pa, vb[1], vb[3]);
            }
        }
    }

    float li0 = 1.0f / l0, li1 = 1.0f / l1;
    int rg0 = qb * 64 + wm + r0;
    int rg1 = rg0 + 8;
    #pragma unroll
    for (int nf = 0; nf < 8; nf++) {
        int col = 8 * nf + 2 * cq;
        uint32_t v0 = ph2(o[nf][0] * li0, o[nf][1] * li0);
        uint32_t v1 = ph2(o[nf][2] * li1, o[nf][3] * li1);
        *reinterpret_cast<uint32_t*>(
            &O[(size_t)(b * TLEN + rg0) * EMB + h * HDIM + col]) = v0;
        *reinterpret_cast<uint32_t*>(
            &O[(size_t)(b * TLEN + rg1) * EMB + h * HDIM + col]) = v1;
    }
}

// ---------------------------------------------------------------------------
// Launcher
// ---------------------------------------------------------------------------
extern "C" void kernel_launch(void* const* d_in, const int* in_sizes, int n_in,
                              void* d_out, int out_size)
{
    const float* x    = (const float*)d_in[0];
    const float* Wk   = (const float*)d_in[1];
    const float* Wq   = (const float*)d_in[2];
    const float* Wv   = (const float*)d_in[3];
    const float* Wu   = (const float*)d_in[4];
    const float* klnw = (const float*)d_in[5];
    const float* klnb = (const float*)d_in[6];
    const float* qlnw = (const float*)d_in[7];
    const float* qlnb = (const float*)d_in[8];
    float* out = (float*)d_out;

    __half *xf, *af, *qh, *kh, *vh, *Wf;
    cudaGetSymbolAddress((void**)&xf, g_xf);
    cudaGetSymbolAddress((void**)&af, g_af);
    cudaGetSymbolAddress((void**)&qh, g_qh);
    cudaGetSymbolAddress((void**)&kh, g_kh);
    cudaGetSymbolAddress((void**)&vh, g_vh);
    cudaGetSymbolAddress((void**)&Wf, g_Wf);

    const int WN = EMB * EMB;

    // Conversions: x (1 launch) + all 4 weights (1 launch)
    cvt_kernel<<<(MROWS * EMB / 4 + 255) / 256, 256>>>(x, xf, MROWS * EMB / 4);
    cvt_w_kernel<<<(4 * WN / 4) / 256, 256>>>(Wk, Wq, Wv, Wu, Wf);

    // Fused QKV projection + LayerNorm epilogue (all fp16 outputs)
    cudaFuncSetAttribute(gemm_qkv_kernel,
                         cudaFuncAttributeMaxDynamicSharedMemorySize, GEMM_SMEM);
    cudaFuncSetAttribute(gemm_fp16_kernel,
                         cudaFuncAttributeMaxDynamicSharedMemorySize, GEMM_SMEM);
    dim3 qkvgrid(3 * EMB / BN, MROWS / BM);
    gemm_qkv_kernel<<<qkvgrid, 256, GEMM_SMEM>>>(xf, Wf, kh, qh, vh,
                                                 klnw, klnb, qlnw, qlnb);

    // Attention (tensor-core FA2), writes fp16 directly into af
    dim3 agrid(TLEN / 64, HEADS, BATCH);
    attn_kernel<<<agrid, 128>>>(qh, kh, vh, af);

    // Output projection
    dim3 ogrid(EMB / BN, MROWS / BM);
    gemm_fp16_kernel<<<ogrid, 256, GEMM_SMEM>>>(af, Wf + 3 * WN, out, MROWS, EMB, EMB);
}